// round 1
// baseline (speedup 1.0000x reference)
#include <cuda_runtime.h>
#include <cuda_bf16.h>
#include <cstddef>

// Problem constants
#define BATCH   8
#define SEQ     1024
#define CEMB    1024
#define NHEAD   16
#define HDIM    64
#define NQS     4
#define MROWS   (BATCH * SEQ)          // 8192
#define QKV_N   ((NQS + 2) * CEMB)     // 6144
#define CAT_N   (NQS * CEMB)           // 4096

// Scratch (allocation-free rule: __device__ globals)
__device__ float g_qkv[(size_t)MROWS * QKV_N];   // [8192, 6144]
__device__ float g_ycat[(size_t)MROWS * CAT_N];  // [8192, 4096]

// ---------------------------------------------------------------------------
// C[M,N] = A[M,K] @ B[N,K]^T   (both A and B are K-major / row-major)
// 128x128 tile, BK=8, 256 threads, 8x8 accum per thread (split 4+4 quadrants)
// Requires M%128==0, N%128==0, K%8==0 (true for all our shapes).
// ---------------------------------------------------------------------------
__global__ __launch_bounds__(256, 2)
void sgemm_nt(const float* __restrict__ A, const float* __restrict__ B,
              float* __restrict__ C, int M, int N, int K)
{
    __shared__ float As[8][128];
    __shared__ float Bs[8][128];

    const int tid  = threadIdx.x;
    const int bm   = blockIdx.y * 128;
    const int bn   = blockIdx.x * 128;

    const int lrow = tid >> 1;        // 0..127
    const int lk   = (tid & 1) * 4;   // 0 or 4

    const float* Aptr = A + (size_t)(bm + lrow) * K + lk;
    const float* Bptr = B + (size_t)(bn + lrow) * K + lk;

    const int tx = tid & 15;          // col group
    const int ty = tid >> 4;          // row group

    float acc[8][8];
#pragma unroll
    for (int i = 0; i < 8; i++)
#pragma unroll
        for (int j = 0; j < 8; j++) acc[i][j] = 0.f;

    for (int k0 = 0; k0 < K; k0 += 8) {
        float4 a4 = *(const float4*)(Aptr + k0);
        float4 b4 = *(const float4*)(Bptr + k0);
        __syncthreads();  // previous tile fully consumed
        As[lk + 0][lrow] = a4.x; As[lk + 1][lrow] = a4.y;
        As[lk + 2][lrow] = a4.z; As[lk + 3][lrow] = a4.w;
        Bs[lk + 0][lrow] = b4.x; Bs[lk + 1][lrow] = b4.y;
        Bs[lk + 2][lrow] = b4.z; Bs[lk + 3][lrow] = b4.w;
        __syncthreads();

#pragma unroll
        for (int kk = 0; kk < 8; kk++) {
            float4 a0 = *(const float4*)&As[kk][ty * 4];
            float4 a1 = *(const float4*)&As[kk][64 + ty * 4];
            float4 b0 = *(const float4*)&Bs[kk][tx * 4];
            float4 b1 = *(const float4*)&Bs[kk][64 + tx * 4];
            float ar[8] = {a0.x, a0.y, a0.z, a0.w, a1.x, a1.y, a1.z, a1.w};
            float br[8] = {b0.x, b0.y, b0.z, b0.w, b1.x, b1.y, b1.z, b1.w};
#pragma unroll
            for (int i = 0; i < 8; i++)
#pragma unroll
                for (int j = 0; j < 8; j++)
                    acc[i][j] = fmaf(ar[i], br[j], acc[i][j]);
        }
    }

#pragma unroll
    for (int ii = 0; ii < 8; ii++) {
        int m = bm + ((ii < 4) ? (ty * 4 + ii) : (64 + ty * 4 + ii - 4));
        float* cp = C + (size_t)m * N + bn;
        *(float4*)(cp + tx * 4) =
            make_float4(acc[ii][0], acc[ii][1], acc[ii][2], acc[ii][3]);
        *(float4*)(cp + 64 + tx * 4) =
            make_float4(acc[ii][4], acc[ii][5], acc[ii][6], acc[ii][7]);
    }
}

// ---------------------------------------------------------------------------
// Flash attention (fp32, causal). One block = 64 query rows of one (b,h,g).
// smem tiles padded to 68 floats per row.
// ---------------------------------------------------------------------------
#define PAD 68
#define ATT_SMEM_FLOATS (4 * 64 * PAD + 128)
#define ATT_SMEM_BYTES  (ATT_SMEM_FLOATS * 4)

__global__ __launch_bounds__(256, 2)
void attn_kernel(const float* __restrict__ qkv, float* __restrict__ ycat)
{
    extern __shared__ float sm[];
    float* Qt      = sm;                  // [64][PAD]  Qt[d*PAD + r]
    float* Kt      = Qt + 64 * PAD;       // [64][PAD]  Kt[d*PAD + c]
    float* Vs      = Kt + 64 * PAD;       // [64][PAD]  Vs[j*PAD + d]
    float* Ss      = Vs + 64 * PAD;       // [64][PAD]  Ss[r*PAD + c]
    float* alpha_s = Ss + 64 * PAD;       // [64]
    float* l_s     = alpha_s + 64;        // [64]

    const int qi  = blockIdx.x;           // 0..15 query tile
    const int bhg = blockIdx.y;           // b*64 + h*4 + g
    const int g = bhg & 3;
    const int h = (bhg >> 2) & 15;
    const int b = bhg >> 6;

    const float* qbase = qkv + (size_t)(b * SEQ) * QKV_N + g * CEMB + h * HDIM;
    const float* kbase = qkv + (size_t)(b * SEQ) * QKV_N + NQS * CEMB + h * HDIM;
    const float* vbase = qkv + (size_t)(b * SEQ) * QKV_N + (NQS + 1) * CEMB + h * HDIM;

    const int tid = threadIdx.x;
    const int tx = tid & 15, ty = tid >> 4;

    // load Q tile (transposed into Qt[d][r])
    for (int idx = tid; idx < 64 * 64; idx += 256) {
        int r = idx >> 6, d = idx & 63;
        Qt[d * PAD + r] = qbase[(size_t)(qi * 64 + r) * QKV_N + d];
    }

    float o[4][4];
#pragma unroll
    for (int i = 0; i < 4; i++)
#pragma unroll
        for (int j = 0; j < 4; j++) o[i][j] = 0.f;

    float m_r = -INFINITY, l_r = 0.f;     // per-row stats (valid for tid<64)

    for (int kj = 0; kj <= qi; kj++) {
        __syncthreads();   // prev O-update finished reading Ss/Vs; Q load done
        for (int idx = tid; idx < 64 * 64; idx += 256) {
            int r = idx >> 6, d = idx & 63;
            float kv = kbase[(size_t)(kj * 64 + r) * QKV_N + d];
            float vv = vbase[(size_t)(kj * 64 + r) * QKV_N + d];
            Kt[d * PAD + r] = kv;
            Vs[r * PAD + d] = vv;
        }
        __syncthreads();

        // S = (Q K^T) * scale   (thread: rows ty*4.., cols tx*4..)
        float s[4][4];
#pragma unroll
        for (int i = 0; i < 4; i++)
#pragma unroll
            for (int j = 0; j < 4; j++) s[i][j] = 0.f;

        for (int d = 0; d < 64; d++) {
            float qv[4], kv[4];
#pragma unroll
            for (int i = 0; i < 4; i++) qv[i] = Qt[d * PAD + ty * 4 + i];
#pragma unroll
            for (int j = 0; j < 4; j++) kv[j] = Kt[d * PAD + tx * 4 + j];
#pragma unroll
            for (int i = 0; i < 4; i++)
#pragma unroll
                for (int j = 0; j < 4; j++)
                    s[i][j] = fmaf(qv[i], kv[j], s[i][j]);
        }
#pragma unroll
        for (int i = 0; i < 4; i++)
#pragma unroll
            for (int j = 0; j < 4; j++)
                Ss[(ty * 4 + i) * PAD + tx * 4 + j] = s[i][j] * 0.125f;
        __syncthreads();

        // online softmax, one thread per row
        if (tid < 64) {
            const int r = tid;
            const int cmax = (kj == qi) ? (r + 1) : 64;   // causal bound
            float mx = -INFINITY;
            for (int c = 0; c < cmax; c++) mx = fmaxf(mx, Ss[r * PAD + c]);
            float nm = fmaxf(m_r, mx);
            float al = __expf(m_r - nm);
            float sum = 0.f;
            for (int c = 0; c < 64; c++) {
                float p = (c < cmax) ? __expf(Ss[r * PAD + c] - nm) : 0.f;
                Ss[r * PAD + c] = p;
                sum += p;
            }
            l_r = l_r * al + sum;
            m_r = nm;
            alpha_s[r] = al;
        }
        __syncthreads();

        // O = O*alpha + P @ V
        float al[4];
#pragma unroll
        for (int i = 0; i < 4; i++) al[i] = alpha_s[ty * 4 + i];
#pragma unroll
        for (int i = 0; i < 4; i++)
#pragma unroll
            for (int j = 0; j < 4; j++) o[i][j] *= al[i];

        for (int jj = 0; jj < 64; jj++) {
            float p[4], vv[4];
#pragma unroll
            for (int i = 0; i < 4; i++) p[i] = Ss[(ty * 4 + i) * PAD + jj];
#pragma unroll
            for (int j = 0; j < 4; j++) vv[j] = Vs[jj * PAD + tx * 4 + j];
#pragma unroll
            for (int i = 0; i < 4; i++)
#pragma unroll
                for (int j = 0; j < 4; j++)
                    o[i][j] = fmaf(p[i], vv[j], o[i][j]);
        }
    }

    if (tid < 64) l_s[tid] = l_r;
    __syncthreads();

    float* ybase = ycat + (size_t)(b * SEQ) * CAT_N + g * CEMB + h * HDIM;
#pragma unroll
    for (int i = 0; i < 4; i++) {
        int r = ty * 4 + i;
        float inv = 1.f / l_s[r];
        *(float4*)&ybase[(size_t)(qi * 64 + r) * CAT_N + tx * 4] =
            make_float4(o[i][0] * inv, o[i][1] * inv, o[i][2] * inv, o[i][3] * inv);
    }
}

// ---------------------------------------------------------------------------
extern "C" void kernel_launch(void* const* d_in, const int* in_sizes, int n_in,
                              void* d_out, int out_size)
{
    const float* x      = (const float*)d_in[0];   // [8,1024,1024]
    const float* W_attn = (const float*)d_in[1];   // [6144,1024]
    const float* W_proj = (const float*)d_in[2];   // [1024,4096]
    float* out = (float*)d_out;                    // [8,1024,1024]

    float* qkv;  cudaGetSymbolAddress((void**)&qkv,  g_qkv);
    float* ycat; cudaGetSymbolAddress((void**)&ycat, g_ycat);

    // 1) qkv = x @ W_attn^T     [8192,6144]
    {
        dim3 grid(QKV_N / 128, MROWS / 128);
        sgemm_nt<<<grid, 256>>>(x, W_attn, qkv, MROWS, QKV_N, CEMB);
    }

    // 2) flash attention per (b,h,g)
    {
        cudaFuncSetAttribute(attn_kernel,
                             cudaFuncAttributeMaxDynamicSharedMemorySize,
                             ATT_SMEM_BYTES);
        dim3 grid(SEQ / 64, BATCH * NHEAD * NQS);
        attn_kernel<<<grid, 256, ATT_SMEM_BYTES>>>(qkv, ycat);
    }

    // 3) out = ycat @ W_proj^T  [8192,1024]
    {
        dim3 grid(CEMB / 128, MROWS / 128);
        sgemm_nt<<<grid, 256>>>(ycat, W_proj, out, MROWS, CEMB, CAT_N);
    }
}

// round 3
// speedup vs baseline: 1.3967x; 1.3967x over previous
#include <cuda_runtime.h>
#include <cuda_bf16.h>
#include <cstdint>
#include <cstddef>

// Problem constants
#define BATCH   8
#define SEQ     1024
#define CEMB    1024
#define NHEAD   16
#define HDIM    64
#define NQS     4
#define MROWS   (BATCH * SEQ)          // 8192
#define QKV_N   ((NQS + 2) * CEMB)     // 6144
#define CAT_N   (NQS * CEMB)           // 4096

// Scratch (allocation-free rule: __device__ globals)
__device__ float g_qkv [(size_t)MROWS * QKV_N];   // [8192,6144] fp32
__device__ float g_ycat[(size_t)MROWS * CAT_N];   // [8192,4096] fp32
__device__ __nv_bfloat16 g_xhi [(size_t)MROWS * CEMB];
__device__ __nv_bfloat16 g_xlo [(size_t)MROWS * CEMB];
__device__ __nv_bfloat16 g_wahi[(size_t)QKV_N * CEMB];
__device__ __nv_bfloat16 g_walo[(size_t)QKV_N * CEMB];
__device__ __nv_bfloat16 g_ychi[(size_t)MROWS * CAT_N];
__device__ __nv_bfloat16 g_yclo[(size_t)MROWS * CAT_N];
__device__ __nv_bfloat16 g_wphi[(size_t)CEMB * CAT_N];
__device__ __nv_bfloat16 g_wplo[(size_t)CEMB * CAT_N];

// ---------------------------------------------------------------------------
// helpers
// ---------------------------------------------------------------------------
__device__ __forceinline__ uint32_t smem_u32(const void* p) {
    uint32_t a;
    asm("{ .reg .u64 t; cvta.to.shared.u64 t, %1; cvt.u32.u64 %0, t; }"
        : "=r"(a) : "l"(p));
    return a;
}
__device__ __forceinline__ void cp16(uint32_t dst, const void* src) {
    asm volatile("cp.async.cg.shared.global [%0], [%1], 16;" :: "r"(dst), "l"(src) : "memory");
}
#define CP_COMMIT() asm volatile("cp.async.commit_group;" ::: "memory")
#define CP_WAIT(n)  asm volatile("cp.async.wait_group %0;" :: "n"(n) : "memory")

#define LDSM_X4(r0, r1, r2, r3, addr)                                          \
    asm volatile("ldmatrix.sync.aligned.m8n8.x4.shared.b16 {%0,%1,%2,%3}, [%4];" \
                 : "=r"(r0), "=r"(r1), "=r"(r2), "=r"(r3) : "r"(addr))

#define MMA_BF16(d, a, b0, b1)                                                 \
    asm volatile("mma.sync.aligned.m16n8k16.row.col.f32.bf16.bf16.f32 "        \
                 "{%0,%1,%2,%3}, {%4,%5,%6,%7}, {%8,%9}, {%0,%1,%2,%3};"       \
                 : "+f"((d)[0]), "+f"((d)[1]), "+f"((d)[2]), "+f"((d)[3])      \
                 : "r"((a)[0]), "r"((a)[1]), "r"((a)[2]), "r"((a)[3]),         \
                   "r"(b0), "r"(b1))

// ---------------------------------------------------------------------------
// fp32 -> bf16 hi/lo split (elementwise, vectorized by 4)
// ---------------------------------------------------------------------------
__global__ __launch_bounds__(256)
void cvt_hilo(const float* __restrict__ s, __nv_bfloat16* __restrict__ hi,
              __nv_bfloat16* __restrict__ lo, size_t n4)
{
    size_t i = (size_t)blockIdx.x * blockDim.x + threadIdx.x;
    if (i >= n4) return;
    float4 v = ((const float4*)s)[i];
    float vv[4] = {v.x, v.y, v.z, v.w};
    __nv_bfloat16 h[4], l[4];
#pragma unroll
    for (int j = 0; j < 4; j++) {
        h[j] = __float2bfloat16(vv[j]);
        l[j] = __float2bfloat16(vv[j] - __bfloat162float(h[j]));
    }
    __nv_bfloat162* hp = (__nv_bfloat162*)(hi + 4 * i);
    __nv_bfloat162* lp = (__nv_bfloat162*)(lo + 4 * i);
    __nv_bfloat162 a, b;
    a.x = h[0]; a.y = h[1]; hp[0] = a;
    b.x = h[2]; b.y = h[3]; hp[1] = b;
    a.x = l[0]; a.y = l[1]; lp[0] = a;
    b.x = l[2]; b.y = l[3]; lp[1] = b;
}

// ---------------------------------------------------------------------------
// C[M,N] = A[M,K] @ B[N,K]^T via mma.sync bf16, 3-pass hi/lo split.
// CTA tile 128x128, BK=32, cp.async double buffer, 8 warps of 32x64.
// smem tiles: [128][40] bf16 (80-byte row stride -> conflict-free ldmatrix).
// ---------------------------------------------------------------------------
#define BK        32
#define TPAD      40
#define TILE_B    (128 * TPAD * 2)          // 10240 bytes per tile
#define STAGE_B   (4 * TILE_B)              // Ahi|Alo|Bhi|Blo = 40960
#define GEMM_SMEM (2 * STAGE_B)             // 81920

__global__ __launch_bounds__(256, 1)
void gemm_bf16x3(const __nv_bfloat16* __restrict__ Ahi, const __nv_bfloat16* __restrict__ Alo,
                 const __nv_bfloat16* __restrict__ Bhi, const __nv_bfloat16* __restrict__ Blo,
                 float* __restrict__ C, int N, int K)
{
    extern __shared__ __align__(128) char smem[];
    const uint32_t sb = smem_u32(smem);
    const int tid  = threadIdx.x;
    const int lane = tid & 31, wid = tid >> 5;
    const int wm = wid & 3;          // 4 m-tiles of 32
    const int wn = wid >> 2;         // 2 n-tiles of 64
    const int m0 = blockIdx.y * 128;
    const int n0 = blockIdx.x * 128;

    const __nv_bfloat16* srcs[4] = {
        Ahi + (size_t)m0 * K, Alo + (size_t)m0 * K,
        Bhi + (size_t)n0 * K, Blo + (size_t)n0 * K };

    const int NC = K / BK;

    // preload chunk into stage s: 4 tiles x 128 rows x 4 chunks of 16B
    auto preload = [&](int chunk, int s) {
        const uint32_t stg = sb + s * STAGE_B;
        const int k0 = chunk * BK;
#pragma unroll
        for (int it = 0; it < 8; it++) {
            int idx = tid + it * 256;        // 0..2047
            int t = idx >> 9, rem = idx & 511;
            int r = rem >> 2, c = rem & 3;
            cp16(stg + t * TILE_B + r * 80 + c * 16,
                 srcs[t] + (size_t)r * K + k0 + c * 8);
        }
        CP_COMMIT();
    };

    float acc[2][8][4];
#pragma unroll
    for (int i = 0; i < 2; i++)
#pragma unroll
        for (int j = 0; j < 8; j++)
#pragma unroll
            for (int q = 0; q < 4; q++) acc[i][j][q] = 0.f;

    // ldmatrix lane addressing: row = lane&15, col-half = (lane>>4)*8
    const int lrow  = lane & 15;
    const int lcol8 = (lane >> 4) * 8;

    preload(0, 0);

    for (int i = 0; i < NC; i++) {
        const int s = i & 1;
        if (i + 1 < NC) { preload(i + 1, s ^ 1); CP_WAIT(1); }
        else           { CP_WAIT(0); }
        __syncthreads();

        const uint32_t stg = sb + s * STAGE_B;
        const int pa[3] = {0, 0, 1}, pb[3] = {0, 1, 0};
#pragma unroll
        for (int p = 0; p < 3; p++) {
            const uint32_t aT = stg + pa[p] * TILE_B;
            const uint32_t bT = stg + (2 + pb[p]) * TILE_B;
#pragma unroll
            for (int ks = 0; ks < 2; ks++) {
                const int kc = ks * 16 + lcol8;
                uint32_t a[2][4];
#pragma unroll
                for (int mf = 0; mf < 2; mf++) {
                    uint32_t addr = aT + (uint32_t)((wm * 32 + mf * 16 + lrow) * 80 + kc * 2);
                    LDSM_X4(a[mf][0], a[mf][1], a[mf][2], a[mf][3], addr);
                }
                uint32_t b[4][4];
#pragma unroll
                for (int nt = 0; nt < 4; nt++) {
                    uint32_t addr = bT + (uint32_t)((wn * 64 + nt * 16 + lrow) * 80 + kc * 2);
                    LDSM_X4(b[nt][0], b[nt][1], b[nt][2], b[nt][3], addr);
                }
#pragma unroll
                for (int mf = 0; mf < 2; mf++)
#pragma unroll
                    for (int nt = 0; nt < 4; nt++) {
                        // b regs: 0=(n0-7,k0-7) 1=(n8-15,k0-7) 2=(n0-7,k8-15) 3=(n8-15,k8-15)
                        MMA_BF16(acc[mf][2 * nt + 0], a[mf], b[nt][0], b[nt][2]);
                        MMA_BF16(acc[mf][2 * nt + 1], a[mf], b[nt][1], b[nt][3]);
                    }
            }
        }
        __syncthreads();
    }

    // epilogue: direct fp32 stores
#pragma unroll
    for (int mf = 0; mf < 2; mf++) {
        const int row = m0 + wm * 32 + mf * 16 + (lane >> 2);
#pragma unroll
        for (int nf = 0; nf < 8; nf++) {
            const int col = n0 + wn * 64 + nf * 8 + 2 * (lane & 3);
            float* c0 = C + (size_t)row * N + col;
            float* c1 = C + (size_t)(row + 8) * N + col;
            c0[0] = acc[mf][nf][0]; c0[1] = acc[mf][nf][1];
            c1[0] = acc[mf][nf][2]; c1[1] = acc[mf][nf][3];
        }
    }
}

// ---------------------------------------------------------------------------
// Flash attention (fp32, causal) — unchanged from R1
// ---------------------------------------------------------------------------
#define PAD 68
#define ATT_SMEM_FLOATS (4 * 64 * PAD + 128)
#define ATT_SMEM_BYTES  (ATT_SMEM_FLOATS * 4)

__global__ __launch_bounds__(256, 2)
void attn_kernel(const float* __restrict__ qkv, float* __restrict__ ycat)
{
    extern __shared__ float sm[];
    float* Qt      = sm;
    float* Kt      = Qt + 64 * PAD;
    float* Vs      = Kt + 64 * PAD;
    float* Ss      = Vs + 64 * PAD;
    float* alpha_s = Ss + 64 * PAD;
    float* l_s     = alpha_s + 64;

    const int qi  = blockIdx.x;
    const int bhg = blockIdx.y;
    const int g = bhg & 3;
    const int h = (bhg >> 2) & 15;
    const int b = bhg >> 6;

    const float* qbase = qkv + (size_t)(b * SEQ) * QKV_N + g * CEMB + h * HDIM;
    const float* kbase = qkv + (size_t)(b * SEQ) * QKV_N + NQS * CEMB + h * HDIM;
    const float* vbase = qkv + (size_t)(b * SEQ) * QKV_N + (NQS + 1) * CEMB + h * HDIM;

    const int tid = threadIdx.x;
    const int tx = tid & 15, ty = tid >> 4;

    for (int idx = tid; idx < 64 * 64; idx += 256) {
        int r = idx >> 6, d = idx & 63;
        Qt[d * PAD + r] = qbase[(size_t)(qi * 64 + r) * QKV_N + d];
    }

    float o[4][4];
#pragma unroll
    for (int i = 0; i < 4; i++)
#pragma unroll
        for (int j = 0; j < 4; j++) o[i][j] = 0.f;

    float m_r = -INFINITY, l_r = 0.f;

    for (int kj = 0; kj <= qi; kj++) {
        __syncthreads();
        for (int idx = tid; idx < 64 * 64; idx += 256) {
            int r = idx >> 6, d = idx & 63;
            float kv = kbase[(size_t)(kj * 64 + r) * QKV_N + d];
            float vv = vbase[(size_t)(kj * 64 + r) * QKV_N + d];
            Kt[d * PAD + r] = kv;
            Vs[r * PAD + d] = vv;
        }
        __syncthreads();

        float s[4][4];
#pragma unroll
        for (int i = 0; i < 4; i++)
#pragma unroll
            for (int j = 0; j < 4; j++) s[i][j] = 0.f;

        for (int d = 0; d < 64; d++) {
            float qv[4], kv[4];
#pragma unroll
            for (int i = 0; i < 4; i++) qv[i] = Qt[d * PAD + ty * 4 + i];
#pragma unroll
            for (int j = 0; j < 4; j++) kv[j] = Kt[d * PAD + tx * 4 + j];
#pragma unroll
            for (int i = 0; i < 4; i++)
#pragma unroll
                for (int j = 0; j < 4; j++)
                    s[i][j] = fmaf(qv[i], kv[j], s[i][j]);
        }
#pragma unroll
        for (int i = 0; i < 4; i++)
#pragma unroll
            for (int j = 0; j < 4; j++)
                Ss[(ty * 4 + i) * PAD + tx * 4 + j] = s[i][j] * 0.125f;
        __syncthreads();

        if (tid < 64) {
            const int r = tid;
            const int cmax = (kj == qi) ? (r + 1) : 64;
            float mx = -INFINITY;
            for (int c = 0; c < cmax; c++) mx = fmaxf(mx, Ss[r * PAD + c]);
            float nm = fmaxf(m_r, mx);
            float al = __expf(m_r - nm);
            float sum = 0.f;
            for (int c = 0; c < 64; c++) {
                float p = (c < cmax) ? __expf(Ss[r * PAD + c] - nm) : 0.f;
                Ss[r * PAD + c] = p;
                sum += p;
            }
            l_r = l_r * al + sum;
            m_r = nm;
            alpha_s[r] = al;
        }
        __syncthreads();

        float al[4];
#pragma unroll
        for (int i = 0; i < 4; i++) al[i] = alpha_s[ty * 4 + i];
#pragma unroll
        for (int i = 0; i < 4; i++)
#pragma unroll
            for (int j = 0; j < 4; j++) o[i][j] *= al[i];

        for (int jj = 0; jj < 64; jj++) {
            float p[4], vv[4];
#pragma unroll
            for (int i = 0; i < 4; i++) p[i] = Ss[(ty * 4 + i) * PAD + jj];
#pragma unroll
            for (int j = 0; j < 4; j++) vv[j] = Vs[jj * PAD + tx * 4 + j];
#pragma unroll
            for (int i = 0; i < 4; i++)
#pragma unroll
                for (int j = 0; j < 4; j++)
                    o[i][j] = fmaf(p[i], vv[j], o[i][j]);
        }
    }

    if (tid < 64) l_s[tid] = l_r;
    __syncthreads();

    float* ybase = ycat + (size_t)(b * SEQ) * CAT_N + g * CEMB + h * HDIM;
#pragma unroll
    for (int i = 0; i < 4; i++) {
        int r = ty * 4 + i;
        float inv = 1.f / l_s[r];
        *(float4*)&ybase[(size_t)(qi * 64 + r) * CAT_N + tx * 4] =
            make_float4(o[i][0] * inv, o[i][1] * inv, o[i][2] * inv, o[i][3] * inv);
    }
}

// ---------------------------------------------------------------------------
extern "C" void kernel_launch(void* const* d_in, const int* in_sizes, int n_in,
                              void* d_out, int out_size)
{
    const float* x      = (const float*)d_in[0];   // [8,1024,1024]
    const float* W_attn = (const float*)d_in[1];   // [6144,1024]
    const float* W_proj = (const float*)d_in[2];   // [1024,4096]
    float* out = (float*)d_out;                    // [8,1024,1024]

    float *qkv, *ycat;
    __nv_bfloat16 *xhi, *xlo, *wahi, *walo, *ychi, *yclo, *wphi, *wplo;
    cudaGetSymbolAddress((void**)&qkv,  g_qkv);
    cudaGetSymbolAddress((void**)&ycat, g_ycat);
    cudaGetSymbolAddress((void**)&xhi,  g_xhi);
    cudaGetSymbolAddress((void**)&xlo,  g_xlo);
    cudaGetSymbolAddress((void**)&wahi, g_wahi);
    cudaGetSymbolAddress((void**)&walo, g_walo);
    cudaGetSymbolAddress((void**)&ychi, g_ychi);
    cudaGetSymbolAddress((void**)&yclo, g_yclo);
    cudaGetSymbolAddress((void**)&wphi, g_wphi);
    cudaGetSymbolAddress((void**)&wplo, g_wplo);

    cudaFuncSetAttribute(gemm_bf16x3,
                         cudaFuncAttributeMaxDynamicSharedMemorySize, GEMM_SMEM);
    cudaFuncSetAttribute(attn_kernel,
                         cudaFuncAttributeMaxDynamicSharedMemorySize, ATT_SMEM_BYTES);

    // 0) hi/lo conversions for GEMM1 operands
    {
        size_t n4 = (size_t)MROWS * CEMB / 4;
        cvt_hilo<<<(unsigned)((n4 + 255) / 256), 256>>>(x, xhi, xlo, n4);
        n4 = (size_t)QKV_N * CEMB / 4;
        cvt_hilo<<<(unsigned)((n4 + 255) / 256), 256>>>(W_attn, wahi, walo, n4);
    }

    // 1) qkv = x @ W_attn^T  (mma.sync bf16, 3-pass)
    {
        dim3 grid(QKV_N / 128, MROWS / 128);
        gemm_bf16x3<<<grid, 256, GEMM_SMEM>>>(xhi, xlo, wahi, walo, qkv, QKV_N, CEMB);
    }

    // 2) flash attention per (b,h,g)
    {
        dim3 grid(SEQ / 64, BATCH * NHEAD * NQS);
        attn_kernel<<<grid, 256, ATT_SMEM_BYTES>>>(qkv, ycat);
    }

    // 3) hi/lo conversions for GEMM2 operands
    {
        size_t n4 = (size_t)MROWS * CAT_N / 4;
        cvt_hilo<<<(unsigned)((n4 + 255) / 256), 256>>>(ycat, ychi, yclo, n4);
        n4 = (size_t)CEMB * CAT_N / 4;
        cvt_hilo<<<(unsigned)((n4 + 255) / 256), 256>>>(W_proj, wphi, wplo, n4);
    }

    // 4) out = ycat @ W_proj^T  (mma.sync bf16, 3-pass)
    {
        dim3 grid(CEMB / 128, MROWS / 128);
        gemm_bf16x3<<<grid, 256, GEMM_SMEM>>>(ychi, yclo, wphi, wplo, out, CEMB, CAT_N);
    }
}

// round 10
// speedup vs baseline: 1.5118x; 1.0824x over previous
#include <cuda_runtime.h>
#include <cuda_bf16.h>
#include <cstdint>
#include <cstddef>

// Problem constants
#define BATCH   8
#define SEQ     1024
#define CEMB    1024
#define NHEAD   16
#define HDIM    64
#define NQS     4
#define MROWS   (BATCH * SEQ)          // 8192
#define QKV_N   ((NQS + 2) * CEMB)     // 6144
#define CAT_N   (NQS * CEMB)           // 4096

// Scratch (allocation-free rule: __device__ globals)
__device__ float g_qkv [(size_t)MROWS * QKV_N];   // [8192,6144] fp32
__device__ float g_ycat[(size_t)MROWS * CAT_N];   // [8192,4096] fp32
__device__ __nv_bfloat16 g_xhi [(size_t)MROWS * CEMB];
__device__ __nv_bfloat16 g_xlo [(size_t)MROWS * CEMB];
__device__ __nv_bfloat16 g_wahi[(size_t)QKV_N * CEMB];
__device__ __nv_bfloat16 g_walo[(size_t)QKV_N * CEMB];
__device__ __nv_bfloat16 g_ychi[(size_t)MROWS * CAT_N];
__device__ __nv_bfloat16 g_yclo[(size_t)MROWS * CAT_N];
__device__ __nv_bfloat16 g_wphi[(size_t)CEMB * CAT_N];
__device__ __nv_bfloat16 g_wplo[(size_t)CEMB * CAT_N];

// ---------------------------------------------------------------------------
// helpers
// ---------------------------------------------------------------------------
__device__ __forceinline__ uint32_t smem_u32(const void* p) {
    uint32_t a;
    asm("{ .reg .u64 t; cvta.to.shared.u64 t, %1; cvt.u32.u64 %0, t; }"
        : "=r"(a) : "l"(p));
    return a;
}
__device__ __forceinline__ void cp16(uint32_t dst, const void* src) {
    asm volatile("cp.async.cg.shared.global [%0], [%1], 16;" :: "r"(dst), "l"(src) : "memory");
}
#define CP_COMMIT() asm volatile("cp.async.commit_group;" ::: "memory")
#define CP_WAIT(n)  asm volatile("cp.async.wait_group %0;" :: "n"(n) : "memory")

#define LDSM_X4(r0, r1, r2, r3, addr)                                          \
    asm volatile("ldmatrix.sync.aligned.m8n8.x4.shared.b16 {%0,%1,%2,%3}, [%4];" \
                 : "=r"(r0), "=r"(r1), "=r"(r2), "=r"(r3) : "r"(addr))

#define MMA_BF16(d, a, b0, b1)                                                 \
    asm volatile("mma.sync.aligned.m16n8k16.row.col.f32.bf16.bf16.f32 "        \
                 "{%0,%1,%2,%3}, {%4,%5,%6,%7}, {%8,%9}, {%0,%1,%2,%3};"       \
                 : "+f"((d)[0]), "+f"((d)[1]), "+f"((d)[2]), "+f"((d)[3])      \
                 : "r"((a)[0]), "r"((a)[1]), "r"((a)[2]), "r"((a)[3]),         \
                   "r"(b0), "r"(b1))

__device__ __forceinline__ void store_hilo2(float a, float b,
                                            __nv_bfloat16* hi, __nv_bfloat16* lo) {
    __nv_bfloat162 hv, lv;
    hv.x = __float2bfloat16(a); hv.y = __float2bfloat16(b);
    lv.x = __float2bfloat16(a - __bfloat162float(hv.x));
    lv.y = __float2bfloat16(b - __bfloat162float(hv.y));
    *(__nv_bfloat162*)hi = hv;
    *(__nv_bfloat162*)lo = lv;
}

// ---------------------------------------------------------------------------
// fp32 -> bf16 hi/lo split
// ---------------------------------------------------------------------------
__global__ __launch_bounds__(256)
void cvt_hilo(const float* __restrict__ s, __nv_bfloat16* __restrict__ hi,
              __nv_bfloat16* __restrict__ lo, size_t n4)
{
    size_t i = (size_t)blockIdx.x * blockDim.x + threadIdx.x;
    if (i >= n4) return;
    float4 v = ((const float4*)s)[i];
    store_hilo2(v.x, v.y, hi + 4 * i, lo + 4 * i);
    store_hilo2(v.z, v.w, hi + 4 * i + 2, lo + 4 * i + 2);
}

// ---------------------------------------------------------------------------
// C[M,N] = A[M,K] @ B[N,K]^T via mma.sync bf16, 3-pass hi/lo split.
// CTA tile 128x128, BK=32, cp.async double buffer, 8 warps of 32x64.
// EXACT R3-proven kernel (fp32 C output).
// ---------------------------------------------------------------------------
#define BK        32
#define TPAD      40
#define TILE_B    (128 * TPAD * 2)
#define STAGE_B   (4 * TILE_B)
#define GEMM_SMEM (2 * STAGE_B)

__global__ __launch_bounds__(256, 1)
void gemm_bf16x3(const __nv_bfloat16* __restrict__ Ahi, const __nv_bfloat16* __restrict__ Alo,
                 const __nv_bfloat16* __restrict__ Bhi, const __nv_bfloat16* __restrict__ Blo,
                 float* __restrict__ C, int N, int K)
{
    extern __shared__ __align__(128) char smem[];
    const uint32_t sb = smem_u32(smem);
    const int tid  = threadIdx.x;
    const int lane = tid & 31, wid = tid >> 5;
    const int wm = wid & 3;
    const int wn = wid >> 2;
    const int m0 = blockIdx.y * 128;
    const int n0 = blockIdx.x * 128;

    const __nv_bfloat16* srcs[4] = {
        Ahi + (size_t)m0 * K, Alo + (size_t)m0 * K,
        Bhi + (size_t)n0 * K, Blo + (size_t)n0 * K };

    const int NC = K / BK;

    auto preload = [&](int chunk, int s) {
        const uint32_t stg = sb + s * STAGE_B;
        const int k0 = chunk * BK;
#pragma unroll
        for (int it = 0; it < 8; it++) {
            int idx = tid + it * 256;
            int t = idx >> 9, rem = idx & 511;
            int r = rem >> 2, c = rem & 3;
            cp16(stg + t * TILE_B + r * 80 + c * 16,
                 srcs[t] + (size_t)r * K + k0 + c * 8);
        }
        CP_COMMIT();
    };

    float acc[2][8][4];
#pragma unroll
    for (int i = 0; i < 2; i++)
#pragma unroll
        for (int j = 0; j < 8; j++)
#pragma unroll
            for (int q = 0; q < 4; q++) acc[i][j][q] = 0.f;

    const int lrow  = lane & 15;
    const int lcol8 = (lane >> 4) * 8;

    preload(0, 0);

    for (int i = 0; i < NC; i++) {
        const int s = i & 1;
        if (i + 1 < NC) { preload(i + 1, s ^ 1); CP_WAIT(1); }
        else           { CP_WAIT(0); }
        __syncthreads();

        const uint32_t stg = sb + s * STAGE_B;
        const int pa[3] = {0, 0, 1}, pb[3] = {0, 1, 0};
#pragma unroll
        for (int p = 0; p < 3; p++) {
            const uint32_t aT = stg + pa[p] * TILE_B;
            const uint32_t bT = stg + (2 + pb[p]) * TILE_B;
#pragma unroll
            for (int ks = 0; ks < 2; ks++) {
                const int kc = ks * 16 + lcol8;
                uint32_t a[2][4];
#pragma unroll
                for (int mf = 0; mf < 2; mf++) {
                    uint32_t addr = aT + (uint32_t)((wm * 32 + mf * 16 + lrow) * 80 + kc * 2);
                    LDSM_X4(a[mf][0], a[mf][1], a[mf][2], a[mf][3], addr);
                }
                uint32_t b[4][4];
#pragma unroll
                for (int nt = 0; nt < 4; nt++) {
                    uint32_t addr = bT + (uint32_t)((wn * 64 + nt * 16 + lrow) * 80 + kc * 2);
                    LDSM_X4(b[nt][0], b[nt][1], b[nt][2], b[nt][3], addr);
                }
#pragma unroll
                for (int mf = 0; mf < 2; mf++)
#pragma unroll
                    for (int nt = 0; nt < 4; nt++) {
                        MMA_BF16(acc[mf][2 * nt + 0], a[mf], b[nt][0], b[nt][2]);
                        MMA_BF16(acc[mf][2 * nt + 1], a[mf], b[nt][1], b[nt][3]);
                    }
            }
        }
        __syncthreads();
    }

#pragma unroll
    for (int mf = 0; mf < 2; mf++) {
        const int row = m0 + wm * 32 + mf * 16 + (lane >> 2);
#pragma unroll
        for (int nf = 0; nf < 8; nf++) {
            const int col = n0 + wn * 64 + nf * 8 + 2 * (lane & 3);
            float* c0 = C + (size_t)row * N + col;
            float* c1 = C + (size_t)(row + 8) * N + col;
            c0[0] = acc[mf][nf][0]; c0[1] = acc[mf][nf][1];
            c1[0] = acc[mf][nf][2]; c1[1] = acc[mf][nf][3];
        }
    }
}

// ---------------------------------------------------------------------------
// Flash attention (fp32, causal) — R3-proven structure with PARALLEL softmax:
// each thread reduces its own 4x4 S-fragment in registers; row stats via
// shfl_xor across the 16 threads sharing a row (lane bits 0-3 = tx).
// ---------------------------------------------------------------------------
#define PAD 68
#define ATT_SMEM_FLOATS (4 * 64 * PAD)
#define ATT_SMEM_BYTES  (ATT_SMEM_FLOATS * 4)

__global__ __launch_bounds__(256, 2)
void attn_kernel(const float* __restrict__ qkv, float* __restrict__ ycat)
{
    extern __shared__ float sm[];
    float* Qt = sm;                  // [64][PAD]  Qt[d*PAD + r]
    float* Kt = Qt + 64 * PAD;       // [64][PAD]  Kt[d*PAD + c]
    float* Vs = Kt + 64 * PAD;       // [64][PAD]  Vs[j*PAD + d]
    float* Ss = Vs + 64 * PAD;       // [64][PAD]  Ss[r*PAD + c]  (holds P)

    const int qi  = blockIdx.x;
    const int bhg = blockIdx.y;
    const int g = bhg & 3;
    const int h = (bhg >> 2) & 15;
    const int b = bhg >> 6;

    const float* qbase = qkv + (size_t)(b * SEQ) * QKV_N + g * CEMB + h * HDIM;
    const float* kbase = qkv + (size_t)(b * SEQ) * QKV_N + NQS * CEMB + h * HDIM;
    const float* vbase = qkv + (size_t)(b * SEQ) * QKV_N + (NQS + 1) * CEMB + h * HDIM;

    const int tid = threadIdx.x;
    const int tx = tid & 15, ty = tid >> 4;

    // load Q tile (transposed into Qt[d][r])
    for (int idx = tid; idx < 64 * 64; idx += 256) {
        int r = idx >> 6, d = idx & 63;
        Qt[d * PAD + r] = qbase[(size_t)(qi * 64 + r) * QKV_N + d];
    }

    float o[4][4];
#pragma unroll
    for (int i = 0; i < 4; i++)
#pragma unroll
        for (int j = 0; j < 4; j++) o[i][j] = 0.f;

    float m_r[4], l_r[4];            // per-row stats, replicated across tx
#pragma unroll
    for (int i = 0; i < 4; i++) { m_r[i] = -INFINITY; l_r[i] = 0.f; }

    const int rowg0 = qi * 64 + ty * 4;   // this thread's first global q-row

    for (int kj = 0; kj <= qi; kj++) {
        __syncthreads();   // prior iteration's Kt/Vs/Ss reads complete
        for (int idx = tid; idx < 64 * 64; idx += 256) {
            int r = idx >> 6, d = idx & 63;
            float kv = kbase[(size_t)(kj * 64 + r) * QKV_N + d];
            float vv = vbase[(size_t)(kj * 64 + r) * QKV_N + d];
            Kt[d * PAD + r] = kv;
            Vs[r * PAD + d] = vv;
        }
        __syncthreads();

        // S = (Q K^T)  (thread: rows ty*4.., cols tx*4..)
        float s[4][4];
#pragma unroll
        for (int i = 0; i < 4; i++)
#pragma unroll
            for (int j = 0; j < 4; j++) s[i][j] = 0.f;

        for (int d = 0; d < 64; d++) {
            float qv[4], kv[4];
#pragma unroll
            for (int i = 0; i < 4; i++) qv[i] = Qt[d * PAD + ty * 4 + i];
#pragma unroll
            for (int j = 0; j < 4; j++) kv[j] = Kt[d * PAD + tx * 4 + j];
#pragma unroll
            for (int i = 0; i < 4; i++)
#pragma unroll
                for (int j = 0; j < 4; j++)
                    s[i][j] = fmaf(qv[i], kv[j], s[i][j]);
        }

        // scale + causal mask (global col > global row -> -inf)
        const int colg0 = kj * 64 + tx * 4;
#pragma unroll
        for (int i = 0; i < 4; i++) {
            const int rowg = rowg0 + i;
#pragma unroll
            for (int j = 0; j < 4; j++)
                s[i][j] = (colg0 + j > rowg) ? -INFINITY : s[i][j] * 0.125f;
        }

        // parallel online softmax: reduce across the 16 tx-threads of each row
#pragma unroll
        for (int i = 0; i < 4; i++) {
            float mx = fmaxf(fmaxf(s[i][0], s[i][1]), fmaxf(s[i][2], s[i][3]));
#pragma unroll
            for (int dd = 8; dd >= 1; dd >>= 1)
                mx = fmaxf(mx, __shfl_xor_sync(0xffffffffu, mx, dd));

            float nm = fmaxf(m_r[i], mx);
            float al = __expf(m_r[i] - nm);
            m_r[i] = nm;

            float p0 = __expf(s[i][0] - nm);
            float p1 = __expf(s[i][1] - nm);
            float p2 = __expf(s[i][2] - nm);
            float p3 = __expf(s[i][3] - nm);
            float sum = (p0 + p1) + (p2 + p3);
#pragma unroll
            for (int dd = 8; dd >= 1; dd >>= 1)
                sum += __shfl_xor_sync(0xffffffffu, sum, dd);
            l_r[i] = l_r[i] * al + sum;

            // rescale O and stash P
#pragma unroll
            for (int j = 0; j < 4; j++) o[i][j] *= al;
            float* srow = &Ss[(ty * 4 + i) * PAD + tx * 4];
            srow[0] = p0; srow[1] = p1; srow[2] = p2; srow[3] = p3;
        }
        __syncthreads();   // P visible to all

        // O += P @ V
        for (int jj = 0; jj < 64; jj++) {
            float p[4], vv[4];
#pragma unroll
            for (int i = 0; i < 4; i++) p[i] = Ss[(ty * 4 + i) * PAD + jj];
#pragma unroll
            for (int j = 0; j < 4; j++) vv[j] = Vs[jj * PAD + tx * 4 + j];
#pragma unroll
            for (int i = 0; i < 4; i++)
#pragma unroll
                for (int j = 0; j < 4; j++)
                    o[i][j] = fmaf(p[i], vv[j], o[i][j]);
        }
    }

    float* ybase = ycat + (size_t)(b * SEQ) * CAT_N + g * CEMB + h * HDIM;
#pragma unroll
    for (int i = 0; i < 4; i++) {
        int r = ty * 4 + i;
        float inv = 1.f / l_r[i];
        *(float4*)&ybase[(size_t)(qi * 64 + r) * CAT_N + tx * 4] =
            make_float4(o[i][0] * inv, o[i][1] * inv, o[i][2] * inv, o[i][3] * inv);
    }
}

// ---------------------------------------------------------------------------
extern "C" void kernel_launch(void* const* d_in, const int* in_sizes, int n_in,
                              void* d_out, int out_size)
{
    const float* x      = (const float*)d_in[0];   // [8,1024,1024]
    const float* W_attn = (const float*)d_in[1];   // [6144,1024]
    const float* W_proj = (const float*)d_in[2];   // [1024,4096]
    float* out = (float*)d_out;                    // [8,1024,1024]

    float *qkv, *ycat;
    __nv_bfloat16 *xhi, *xlo, *wahi, *walo, *ychi, *yclo, *wphi, *wplo;
    cudaGetSymbolAddress((void**)&qkv,  g_qkv);
    cudaGetSymbolAddress((void**)&ycat, g_ycat);
    cudaGetSymbolAddress((void**)&xhi,  g_xhi);
    cudaGetSymbolAddress((void**)&xlo,  g_xlo);
    cudaGetSymbolAddress((void**)&wahi, g_wahi);
    cudaGetSymbolAddress((void**)&walo, g_walo);
    cudaGetSymbolAddress((void**)&ychi, g_ychi);
    cudaGetSymbolAddress((void**)&yclo, g_yclo);
    cudaGetSymbolAddress((void**)&wphi, g_wphi);
    cudaGetSymbolAddress((void**)&wplo, g_wplo);

    cudaFuncSetAttribute(gemm_bf16x3,
                         cudaFuncAttributeMaxDynamicSharedMemorySize, GEMM_SMEM);
    cudaFuncSetAttribute(attn_kernel,
                         cudaFuncAttributeMaxDynamicSharedMemorySize, ATT_SMEM_BYTES);

    // 0) hi/lo conversions for GEMM1 operands
    {
        size_t n4 = (size_t)MROWS * CEMB / 4;
        cvt_hilo<<<(unsigned)((n4 + 255) / 256), 256>>>(x, xhi, xlo, n4);
        n4 = (size_t)QKV_N * CEMB / 4;
        cvt_hilo<<<(unsigned)((n4 + 255) / 256), 256>>>(W_attn, wahi, walo, n4);
    }

    // 1) qkv = x @ W_attn^T  (mma.sync bf16, 3-pass)
    {
        dim3 grid(QKV_N / 128, MROWS / 128);
        gemm_bf16x3<<<grid, 256, GEMM_SMEM>>>(xhi, xlo, wahi, walo, qkv, QKV_N, CEMB);
    }

    // 2) flash attention per (b,h,g) — parallel softmax
    {
        dim3 grid(SEQ / 64, BATCH * NHEAD * NQS);
        attn_kernel<<<grid, 256, ATT_SMEM_BYTES>>>(qkv, ycat);
    }

    // 3) hi/lo conversions for GEMM2 operands
    {
        size_t n4 = (size_t)MROWS * CAT_N / 4;
        cvt_hilo<<<(unsigned)((n4 + 255) / 256), 256>>>(ycat, ychi, yclo, n4);
        n4 = (size_t)CEMB * CAT_N / 4;
        cvt_hilo<<<(unsigned)((n4 + 255) / 256), 256>>>(W_proj, wphi, wplo, n4);
    }

    // 4) out = ycat @ W_proj^T  (mma.sync bf16, 3-pass)
    {
        dim3 grid(CEMB / 128, MROWS / 128);
        gemm_bf16x3<<<grid, 256, GEMM_SMEM>>>(ychi, yclo, wphi, wplo, out, CEMB, CAT_N);
    }
}